// round 10
// baseline (speedup 1.0000x reference)
#include <cuda_runtime.h>
#include <cuda_bf16.h>
#include <cstdint>

#define B_ 4
#define T_ 4096
#define C_ 1024
#define H_ 64
#define SPLITS 4
#define NEG_BIG (-1e30f)

// Preconverted operands (bf16 hi/lo).
__device__ __nv_bfloat16 g_xh[B_ * T_ * C_];
__device__ __nv_bfloat16 g_xl[B_ * T_ * C_];
__device__ __nv_bfloat16 g_Wh[192 * C_];      // rows: [Wq(64); Wk(64); Wv(64)]
__device__ __nv_bfloat16 g_Wl[192 * C_];
// Projected Q, K bf16 hi/lo [B,T,64]; V transposed hi/lo [B,64,T].
__device__ __nv_bfloat16 g_Qh[B_ * T_ * H_];
__device__ __nv_bfloat16 g_Ql[B_ * T_ * H_];
__device__ __nv_bfloat16 g_Kh[B_ * T_ * H_];
__device__ __nv_bfloat16 g_Kl[B_ * T_ * H_];
__device__ __nv_bfloat16 g_Vth[B_ * H_ * T_];
__device__ __nv_bfloat16 g_Vtl[B_ * H_ * T_];
// Split-K attention partials.
__device__ float g_opart[SPLITS][B_ * T_ * H_];
__device__ float g_m[SPLITS][B_ * T_];
__device__ float g_l[SPLITS][B_ * T_];

// ---------------- bf16 hi/lo split + HMMA mma.sync helpers -----------------
__device__ __forceinline__ void cvt_pair(float a, float b,
                                         uint32_t& hi, uint32_t& lo) {
    __nv_bfloat16 ha = __float2bfloat16(a);
    __nv_bfloat16 hb = __float2bfloat16(b);
    __nv_bfloat16 la = __float2bfloat16(a - __bfloat162float(ha));
    __nv_bfloat16 lb = __float2bfloat16(b - __bfloat162float(hb));
    hi = (uint32_t)__bfloat16_as_ushort(ha) |
         ((uint32_t)__bfloat16_as_ushort(hb) << 16);
    lo = (uint32_t)__bfloat16_as_ushort(la) |
         ((uint32_t)__bfloat16_as_ushort(lb) << 16);
}
__device__ __forceinline__ void cvt_one(float a, uint16_t& hi, uint16_t& lo) {
    __nv_bfloat16 ha = __float2bfloat16(a);
    __nv_bfloat16 la = __float2bfloat16(a - __bfloat162float(ha));
    hi = __bfloat16_as_ushort(ha);
    lo = __bfloat16_as_ushort(la);
}
__device__ __forceinline__ void mma16816(float* d, const uint32_t* a,
                                         uint32_t b0, uint32_t b1) {
    asm volatile(
        "mma.sync.aligned.m16n8k16.row.col.f32.bf16.bf16.f32 "
        "{%0,%1,%2,%3}, {%4,%5,%6,%7}, {%8,%9}, {%0,%1,%2,%3};"
        : "+f"(d[0]), "+f"(d[1]), "+f"(d[2]), "+f"(d[3])
        : "r"(a[0]), "r"(a[1]), "r"(a[2]), "r"(a[3]), "r"(b0), "r"(b1));
}
__device__ __forceinline__ uint32_t cvta_s(const void* p) {
    return (uint32_t)__cvta_generic_to_shared(p);
}
#define LDMX4(R, addr)                                                        \
    asm volatile("ldmatrix.sync.aligned.m8n8.x4.shared.b16 {%0,%1,%2,%3}, [%4];" \
                 : "=r"((R)[0]), "=r"((R)[1]), "=r"((R)[2]), "=r"((R)[3])     \
                 : "r"(addr))

// ---------------------------------------------------------------------------
// Kernel 0: convert x and W to bf16 hi/lo once (bandwidth-bound).
// Grid 8192 blocks for x + 96 for W.
// ---------------------------------------------------------------------------
__global__ __launch_bounds__(256)
void convert_kernel(const float* __restrict__ x,
                    const float* __restrict__ Wk,
                    const float* __restrict__ Wq,
                    const float* __restrict__ Wv) {
    const int t = threadIdx.x;
    const int bid = blockIdx.x;
    if (bid < 8192) {
        const size_t i0 = (size_t)bid * 2048 + (size_t)t * 8;
        const float4 v0 = *(const float4*)(x + i0);
        const float4 v1 = *(const float4*)(x + i0 + 4);
        uint32_t h0, l0, h1, l1, h2, l2, h3, l3;
        cvt_pair(v0.x, v0.y, h0, l0);
        cvt_pair(v0.z, v0.w, h1, l1);
        cvt_pair(v1.x, v1.y, h2, l2);
        cvt_pair(v1.z, v1.w, h3, l3);
        *(uint4*)(g_xh + i0) = make_uint4(h0, h1, h2, h3);
        *(uint4*)(g_xl + i0) = make_uint4(l0, l1, l2, l3);
    } else {
        const size_t off = (size_t)(bid - 8192) * 2048 + (size_t)t * 8;
        const int row = (int)(off >> 10);
        const int col = (int)(off & 1023);
        const float* src = (row < 64)  ? Wq + (size_t)row * C_ + col
                         : (row < 128) ? Wk + (size_t)(row - 64) * C_ + col
                                       : Wv + (size_t)(row - 128) * C_ + col;
        const float4 v0 = *(const float4*)(src);
        const float4 v1 = *(const float4*)(src + 4);
        uint32_t h0, l0, h1, l1, h2, l2, h3, l3;
        cvt_pair(v0.x, v0.y, h0, l0);
        cvt_pair(v0.z, v0.w, h1, l1);
        cvt_pair(v1.x, v1.y, h2, l2);
        cvt_pair(v1.z, v1.w, h3, l3);
        *(uint4*)(g_Wh + off) = make_uint4(h0, h1, h2, h3);
        *(uint4*)(g_Wl + off) = make_uint4(l0, l1, l2, l3);
    }
}

// ---------------------------------------------------------------------------
// Kernel 1: fused QKV projection — pure bf16 HMMA GEMM from preconverted
// operands. Grid (128 M-tiles, 3 N-tiles of 64). Block 256 = 8 warps (4x2).
// Register-prefetch pipelining + ldmatrix fragment loads.
// ---------------------------------------------------------------------------
#define APAD 72
#define SM_ALO (128 * APAD)
#define SM_BHI (2 * 128 * APAD)
#define SM_BLO (2 * 128 * APAD + 64 * APAD)
#define PROJ_SMEM ((2 * 128 * APAD + 2 * 64 * APAD) * 2)

__global__ __launch_bounds__(256, 2)
void proj_mma_kernel() {
    extern __shared__ __nv_bfloat16 sb[];
    __nv_bfloat16* Ahi = sb;
    __nv_bfloat16* Alo = sb + SM_ALO;
    __nv_bfloat16* Bhi = sb + SM_BHI;
    __nv_bfloat16* Blo = sb + SM_BLO;

    const int t    = threadIdx.x;
    const int wid  = t >> 5;
    const int lane = t & 31;
    const int row0 = blockIdx.x * 128;
    const int nt   = blockIdx.y;

    const int wm = wid >> 1, wn = wid & 1;
    const int g = lane >> 2, c = lane & 3;

    // loader mappings (bf16 uint4 units)
    const int arow = t >> 1, acol = (t & 1) * 32;        // A: 4 uint4 per buf
    const int brow = t >> 2, bcol = (t & 3) * 16;        // B: 2 uint4 per buf

    // ldmatrix lane offsets (bytes)
    const uint32_t aoff =
        ((wm * 32 + (lane & 7) + ((lane >> 3) & 1) * 8) * APAD +
         (lane >> 4) * 8) * 2;
    const uint32_t boff =
        ((wn * 32 + (lane & 7) + (lane >> 4) * 8) * APAD +
         ((lane >> 3) & 1) * 8) * 2;
    const uint32_t sAh = cvta_s(Ahi) + aoff, sAl = cvta_s(Alo) + aoff;
    const uint32_t sBh = cvta_s(Bhi) + boff, sBl = cvta_s(Blo) + boff;

    float acc[2][4][4] = {};

    uint4 pAh[4], pAl[4], pBh[2], pBl[2];

    auto load_chunk = [&](int kc) {
        const __nv_bfloat16* ah =
            g_xh + (size_t)(row0 + arow) * C_ + kc * 64 + acol;
        const __nv_bfloat16* al =
            g_xl + (size_t)(row0 + arow) * C_ + kc * 64 + acol;
        #pragma unroll
        for (int u = 0; u < 4; u++) {
            pAh[u] = *(const uint4*)(ah + u * 8);
            pAl[u] = *(const uint4*)(al + u * 8);
        }
        const __nv_bfloat16* bh =
            g_Wh + (size_t)(nt * 64 + brow) * C_ + kc * 64 + bcol;
        const __nv_bfloat16* bl =
            g_Wl + (size_t)(nt * 64 + brow) * C_ + kc * 64 + bcol;
        #pragma unroll
        for (int u = 0; u < 2; u++) {
            pBh[u] = *(const uint4*)(bh + u * 8);
            pBl[u] = *(const uint4*)(bl + u * 8);
        }
    };

    load_chunk(0);

    for (int kc = 0; kc < 16; kc++) {
        // ---- store prefetched chunk to smem ----
        #pragma unroll
        for (int u = 0; u < 4; u++) {
            *(uint4*)(Ahi + arow * APAD + acol + u * 8) = pAh[u];
            *(uint4*)(Alo + arow * APAD + acol + u * 8) = pAl[u];
        }
        #pragma unroll
        for (int u = 0; u < 2; u++) {
            *(uint4*)(Bhi + brow * APAD + bcol + u * 8) = pBh[u];
            *(uint4*)(Blo + brow * APAD + bcol + u * 8) = pBl[u];
        }
        __syncthreads();

        // ---- prefetch next chunk (completes under the mma phase) ----
        if (kc < 15) load_chunk(kc + 1);

        // ---- 3 passes (hh, hl, lh) x 4 k16 of HMMA via ldmatrix ----
        #pragma unroll
        for (int pass = 0; pass < 3; pass++) {
            const uint32_t ab = (pass == 2) ? sAl : sAh;
            const uint32_t bb = (pass == 1) ? sBl : sBh;
            #pragma unroll
            for (int k16 = 0; k16 < 4; k16++) {
                uint32_t A0[4], A1[4], B0[4], B1[4];
                LDMX4(A0, ab + k16 * 32);
                LDMX4(A1, ab + 16 * APAD * 2 + k16 * 32);
                LDMX4(B0, bb + k16 * 32);
                LDMX4(B1, bb + 16 * APAD * 2 + k16 * 32);
                mma16816(acc[0][0], A0, B0[0], B0[1]);
                mma16816(acc[0][1], A0, B0[2], B0[3]);
                mma16816(acc[0][2], A0, B1[0], B1[1]);
                mma16816(acc[0][3], A0, B1[2], B1[3]);
                mma16816(acc[1][0], A1, B0[0], B0[1]);
                mma16816(acc[1][1], A1, B0[2], B0[3]);
                mma16816(acc[1][2], A1, B1[0], B1[1]);
                mma16816(acc[1][3], A1, B1[2], B1[3]);
            }
        }
        __syncthreads();
    }

    // ---- epilogue: convert to bf16 hi/lo and store ----
    if (nt < 2) {
        __nv_bfloat16* dh = (nt == 0) ? g_Qh : g_Kh;
        __nv_bfloat16* dl = (nt == 0) ? g_Ql : g_Kl;
        #pragma unroll
        for (int mi = 0; mi < 2; mi++) {
            const int r = row0 + wm * 32 + mi * 16 + g;
            #pragma unroll
            for (int ni = 0; ni < 4; ni++) {
                const int col = wn * 32 + ni * 8 + c * 2;
                uint32_t h01, l01, h23, l23;
                cvt_pair(acc[mi][ni][0], acc[mi][ni][1], h01, l01);
                cvt_pair(acc[mi][ni][2], acc[mi][ni][3], h23, l23);
                *(uint32_t*)(dh + (size_t)r * H_ + col) = h01;
                *(uint32_t*)(dl + (size_t)r * H_ + col) = l01;
                *(uint32_t*)(dh + (size_t)(r + 8) * H_ + col) = h23;
                *(uint32_t*)(dl + (size_t)(r + 8) * H_ + col) = l23;
            }
        }
    } else {
        // V transposed: g_Vt[b][c][t]
        #pragma unroll
        for (int mi = 0; mi < 2; mi++) {
            const int r = row0 + wm * 32 + mi * 16 + g;
            const int bb = r >> 12;
            const int tt = r & (T_ - 1);
            #pragma unroll
            for (int ni = 0; ni < 4; ni++) {
                const int col = wn * 32 + ni * 8 + c * 2;
                #pragma unroll
                for (int u = 0; u < 4; u++) {
                    const int rr = (u >> 1) * 8;          // 0 or 8
                    const int cc = col + (u & 1);
                    uint16_t h, l;
                    cvt_one(acc[mi][ni][u], h, l);
                    const size_t idx =
                        ((size_t)bb * H_ + cc) * T_ + tt + rr;
                    *(uint16_t*)(g_Vth + idx) = h;
                    *(uint16_t*)(g_Vtl + idx) = l;
                }
            }
        }
    }
}

// ---------------------------------------------------------------------------
// Kernel 2: split-K flash attention on HMMA (unchanged from round 8).
// ---------------------------------------------------------------------------
#define TPAD 72
#define ATTN_SMEM (6 * 64 * TPAD * 2 + 2 * 128 * 4)

__global__ __launch_bounds__(256, 1)
void attn_mma_kernel() {
    extern __shared__ char smraw[];
    __nv_bfloat16* Khs = (__nv_bfloat16*)smraw;
    __nv_bfloat16* Kls = Khs + 64 * TPAD;
    __nv_bfloat16* Vhs = Kls + 64 * TPAD;
    __nv_bfloat16* Vls = Vhs + 64 * TPAD;
    __nv_bfloat16* Phs = Vls + 64 * TPAD;
    __nv_bfloat16* Pls = Phs + 64 * TPAD;
    float* redmax = (float*)(Pls + 64 * TPAD);   // [64][2]
    float* redsum = redmax + 128;                // [64][2]

    const int qb = blockIdx.x, sp = blockIdx.y, b = blockIdx.z;
    const int t = threadIdx.x, wid = t >> 5, lane = t & 31;
    const int wm = wid >> 1, wn = wid & 1;
    const int g = lane >> 2, c = lane & 3;
    const int lr = t >> 2, lc = (t & 3) * 16;

    const size_t base = (size_t)b * T_ * H_;
    const int row_a = wm * 16 + g;

    {
        const size_t off = base + (size_t)(qb * 64 + lr) * H_ + lc;
        *(uint4*)(Phs + lr * TPAD + lc)     = *(const uint4*)(g_Qh + off);
        *(uint4*)(Phs + lr * TPAD + lc + 8) = *(const uint4*)(g_Qh + off + 8);
        *(uint4*)(Pls + lr * TPAD + lc)     = *(const uint4*)(g_Ql + off);
        *(uint4*)(Pls + lr * TPAD + lc + 8) = *(const uint4*)(g_Ql + off + 8);
    }
    __syncthreads();
    uint32_t qh_f[4][4], ql_f[4][4];
    #pragma unroll
    for (int k = 0; k < 4; k++) {
        const __nv_bfloat16* ba = Phs + row_a * TPAD + k * 16 + c * 2;
        qh_f[k][0] = *(const uint32_t*)(ba);
        qh_f[k][1] = *(const uint32_t*)(ba + 8 * TPAD);
        qh_f[k][2] = *(const uint32_t*)(ba + 8);
        qh_f[k][3] = *(const uint32_t*)(ba + 8 * TPAD + 8);
        const __nv_bfloat16* bl = Pls + row_a * TPAD + k * 16 + c * 2;
        ql_f[k][0] = *(const uint32_t*)(bl);
        ql_f[k][1] = *(const uint32_t*)(bl + 8 * TPAD);
        ql_f[k][2] = *(const uint32_t*)(bl + 8);
        ql_f[k][3] = *(const uint32_t*)(bl + 8 * TPAD + 8);
    }
    __syncthreads();

    float o_acc[4][4] = {};
    float m0 = NEG_BIG, m1 = NEG_BIG, l0 = 0.0f, l1 = 0.0f;
    const float sc2 = 1.0f / 64.0f;
    const int kb_max = min(qb + 1, T_ / 64 - 1);

    for (int kb = sp; kb <= kb_max; kb += SPLITS) {
        {
            const size_t koff = base + (size_t)(kb * 64 + lr) * H_ + lc;
            *(uint4*)(Khs + lr * TPAD + lc)     = *(const uint4*)(g_Kh + koff);
            *(uint4*)(Khs + lr * TPAD + lc + 8) = *(const uint4*)(g_Kh + koff + 8);
            *(uint4*)(Kls + lr * TPAD + lc)     = *(const uint4*)(g_Kl + koff);
            *(uint4*)(Kls + lr * TPAD + lc + 8) = *(const uint4*)(g_Kl + koff + 8);
            const size_t voff = ((size_t)b * H_ + lr) * T_ + kb * 64 + lc;
            *(uint4*)(Vhs + lr * TPAD + lc)     = *(const uint4*)(g_Vth + voff);
            *(uint4*)(Vhs + lr * TPAD + lc + 8) = *(const uint4*)(g_Vth + voff + 8);
            *(uint4*)(Vls + lr * TPAD + lc)     = *(const uint4*)(g_Vtl + voff);
            *(uint4*)(Vls + lr * TPAD + lc + 8) = *(const uint4*)(g_Vtl + voff + 8);
        }
        __syncthreads();

        float s_acc[4][4] = {};
        #pragma unroll
        for (int k = 0; k < 4; k++) {
            #pragma unroll
            for (int ni = 0; ni < 4; ni++) {
                const int brow = (wn * 32 + ni * 8 + g) * TPAD + k * 16 + c * 2;
                const uint32_t bh0 = *(const uint32_t*)(Khs + brow);
                const uint32_t bh1 = *(const uint32_t*)(Khs + brow + 8);
                const uint32_t bl0 = *(const uint32_t*)(Kls + brow);
                const uint32_t bl1 = *(const uint32_t*)(Kls + brow + 8);
                mma16816(s_acc[ni], qh_f[k], bh0, bh1);
                mma16816(s_acc[ni], qh_f[k], bl0, bl1);
                mma16816(s_acc[ni], ql_f[k], bh0, bh1);
            }
        }

        const bool need_mask = (kb >= qb);
        const int i0 = qb * 64 + row_a;
        float sv[4][4];
        float rm0 = NEG_BIG, rm1 = NEG_BIG;
        #pragma unroll
        for (int ni = 0; ni < 4; ni++) {
            const int j0 = kb * 64 + wn * 32 + ni * 8 + c * 2;
            float v0 = s_acc[ni][0] * sc2;
            float v1 = s_acc[ni][1] * sc2;
            float v2 = s_acc[ni][2] * sc2;
            float v3 = s_acc[ni][3] * sc2;
            if (need_mask) {
                if (j0     > i0 + 1) v0 = NEG_BIG;
                if (j0 + 1 > i0 + 1) v1 = NEG_BIG;
                if (j0     > i0 + 9) v2 = NEG_BIG;
                if (j0 + 1 > i0 + 9) v3 = NEG_BIG;
            }
            sv[ni][0] = v0; sv[ni][1] = v1; sv[ni][2] = v2; sv[ni][3] = v3;
            rm0 = fmaxf(rm0, fmaxf(v0, v1));
            rm1 = fmaxf(rm1, fmaxf(v2, v3));
        }
        rm0 = fmaxf(rm0, __shfl_xor_sync(0xffffffffu, rm0, 1));
        rm0 = fmaxf(rm0, __shfl_xor_sync(0xffffffffu, rm0, 2));
        rm1 = fmaxf(rm1, __shfl_xor_sync(0xffffffffu, rm1, 1));
        rm1 = fmaxf(rm1, __shfl_xor_sync(0xffffffffu, rm1, 2));
        redmax[(row_a)     * 2 + wn] = rm0;
        redmax[(row_a + 8) * 2 + wn] = rm1;
        __syncthreads();
        rm0 = fmaxf(redmax[row_a * 2], redmax[row_a * 2 + 1]);
        rm1 = fmaxf(redmax[(row_a + 8) * 2], redmax[(row_a + 8) * 2 + 1]);
        const float mn0 = fmaxf(m0, rm0);
        const float mn1 = fmaxf(m1, rm1);
        const float f0 = __expf(m0 - mn0);
        const float f1 = __expf(m1 - mn1);
        m0 = mn0; m1 = mn1;

        float rs0 = 0.0f, rs1 = 0.0f;
        #pragma unroll
        for (int ni = 0; ni < 4; ni++) {
            const float e0 = (sv[ni][0] > -5e29f) ? __expf(sv[ni][0] - mn0) : 0.0f;
            const float e1 = (sv[ni][1] > -5e29f) ? __expf(sv[ni][1] - mn0) : 0.0f;
            const float e2 = (sv[ni][2] > -5e29f) ? __expf(sv[ni][2] - mn1) : 0.0f;
            const float e3 = (sv[ni][3] > -5e29f) ? __expf(sv[ni][3] - mn1) : 0.0f;
            rs0 += e0 + e1;
            rs1 += e2 + e3;
            uint32_t h01, l01, h23, l23;
            cvt_pair(e0, e1, h01, l01);
            cvt_pair(e2, e3, h23, l23);
            const int col = wn * 32 + ni * 8 + c * 2;
            *(uint32_t*)(Phs + (row_a)     * TPAD + col) = h01;
            *(uint32_t*)(Pls + (row_a)     * TPAD + col) = l01;
            *(uint32_t*)(Phs + (row_a + 8) * TPAD + col) = h23;
            *(uint32_t*)(Pls + (row_a + 8) * TPAD + col) = l23;
        }
        rs0 += __shfl_xor_sync(0xffffffffu, rs0, 1);
        rs0 += __shfl_xor_sync(0xffffffffu, rs0, 2);
        rs1 += __shfl_xor_sync(0xffffffffu, rs1, 1);
        rs1 += __shfl_xor_sync(0xffffffffu, rs1, 2);
        redsum[(row_a)     * 2 + wn] = rs0;
        redsum[(row_a + 8) * 2 + wn] = rs1;

        #pragma unroll
        for (int ni = 0; ni < 4; ni++) {
            o_acc[ni][0] *= f0; o_acc[ni][1] *= f0;
            o_acc[ni][2] *= f1; o_acc[ni][3] *= f1;
        }
        __syncthreads();
        l0 = l0 * f0 + redsum[row_a * 2] + redsum[row_a * 2 + 1];
        l1 = l1 * f1 + redsum[(row_a + 8) * 2] + redsum[(row_a + 8) * 2 + 1];

        #pragma unroll
        for (int k = 0; k < 4; k++) {
            uint32_t ph[4], pl[4];
            const __nv_bfloat16* pa = Phs + row_a * TPAD + k * 16 + c * 2;
            ph[0] = *(const uint32_t*)(pa);
            ph[1] = *(const uint32_t*)(pa + 8 * TPAD);
            ph[2] = *(const uint32_t*)(pa + 8);
            ph[3] = *(const uint32_t*)(pa + 8 * TPAD + 8);
            const __nv_bfloat16* pb = Pls + row_a * TPAD + k * 16 + c * 2;
            pl[0] = *(const uint32_t*)(pb);
            pl[1] = *(const uint32_t*)(pb + 8 * TPAD);
            pl[2] = *(const uint32_t*)(pb + 8);
            pl[3] = *(const uint32_t*)(pb + 8 * TPAD + 8);
            #pragma unroll
            for (int ni = 0; ni < 4; ni++) {
                const int brow = (wn * 32 + ni * 8 + g) * TPAD + k * 16 + c * 2;
                const uint32_t vh0 = *(const uint32_t*)(Vhs + brow);
                const uint32_t vh1 = *(const uint32_t*)(Vhs + brow + 8);
                const uint32_t vl0 = *(const uint32_t*)(Vls + brow);
                const uint32_t vl1 = *(const uint32_t*)(Vls + brow + 8);
                mma16816(o_acc[ni], ph, vh0, vh1);
                mma16816(o_acc[ni], ph, vl0, vl1);
                mma16816(o_acc[ni], pl, vh0, vh1);
            }
        }
        __syncthreads();
    }

    const size_t rb = (size_t)b * T_ + qb * 64;
    #pragma unroll
    for (int ni = 0; ni < 4; ni++) {
        const int col = wn * 32 + ni * 8 + c * 2;
        float2 v0; v0.x = o_acc[ni][0]; v0.y = o_acc[ni][1];
        float2 v1; v1.x = o_acc[ni][2]; v1.y = o_acc[ni][3];
        *(float2*)(g_opart[sp] + (rb + row_a) * 64 + col) = v0;
        *(float2*)(g_opart[sp] + (rb + row_a + 8) * 64 + col) = v1;
    }
    if (c == 0 && wn == 0) {
        g_m[sp][rb + row_a] = m0;
        g_l[sp][rb + row_a] = l0;
        g_m[sp][rb + row_a + 8] = m1;
        g_l[sp][rb + row_a + 8] = l1;
    }
}

// ---------------------------------------------------------------------------
// Kernel 3: combine split partials.
// ---------------------------------------------------------------------------
__global__ __launch_bounds__(256)
void combine_kernel(float* __restrict__ out) {
    const int t = threadIdx.x;
    const size_t r = (size_t)blockIdx.x * 16 + (t >> 4);
    const int c = (t & 15) * 4;

    float mv[SPLITS], lv[SPLITS];
    float M = NEG_BIG;
    #pragma unroll
    for (int s = 0; s < SPLITS; s++) {
        mv[s] = g_m[s][r];
        lv[s] = g_l[s][r];
        M = fmaxf(M, mv[s]);
    }
    float w[SPLITS], L = 0.0f;
    #pragma unroll
    for (int s = 0; s < SPLITS; s++) {
        w[s] = __expf(mv[s] - M);
        L += lv[s] * w[s];
    }
    float4 acc = make_float4(0.f, 0.f, 0.f, 0.f);
    #pragma unroll
    for (int s = 0; s < SPLITS; s++) {
        const float4 o = *(const float4*)(g_opart[s] + r * 64 + c);
        acc.x += w[s] * o.x; acc.y += w[s] * o.y;
        acc.z += w[s] * o.z; acc.w += w[s] * o.w;
    }
    const float inv = 1.0f / L;
    float4 ov;
    ov.x = acc.x * inv; ov.y = acc.y * inv;
    ov.z = acc.z * inv; ov.w = acc.w * inv;
    *(float4*)(out + r * 64 + c) = ov;
}

// ---------------------------------------------------------------------------
// Launch
// ---------------------------------------------------------------------------
extern "C" void kernel_launch(void* const* d_in, const int* in_sizes, int n_in,
                              void* d_out, int out_size) {
    const float* x  = (const float*)d_in[0];
    const float* Wk = (const float*)d_in[1];
    const float* Wq = (const float*)d_in[2];
    const float* Wv = (const float*)d_in[3];
    float* out = (float*)d_out;

    cudaFuncSetAttribute(proj_mma_kernel,
                         cudaFuncAttributeMaxDynamicSharedMemorySize, PROJ_SMEM);
    cudaFuncSetAttribute(attn_mma_kernel,
                         cudaFuncAttributeMaxDynamicSharedMemorySize, ATTN_SMEM);

    convert_kernel<<<8192 + 96, 256>>>(x, Wk, Wq, Wv);
    proj_mma_kernel<<<dim3((B_ * T_) / 128, 3), 256, PROJ_SMEM>>>();
    attn_mma_kernel<<<dim3(T_ / 64, SPLITS, B_), 256, ATTN_SMEM>>>();
    combine_kernel<<<(B_ * T_) / 16, 256>>>(out);
}

// round 12
// speedup vs baseline: 1.2802x; 1.2802x over previous
#include <cuda_runtime.h>
#include <cuda_bf16.h>
#include <cstdint>

#define B_ 4
#define T_ 4096
#define C_ 1024
#define H_ 64
#define SPLITS 4
#define NEG_BIG (-1e30f)

// Preconverted operands (bf16 hi/lo).
__device__ __nv_bfloat16 g_xh[B_ * T_ * C_];
__device__ __nv_bfloat16 g_xl[B_ * T_ * C_];
__device__ __nv_bfloat16 g_Wh[192 * C_];      // rows: [Wq(64); Wk(64); Wv(64)]
__device__ __nv_bfloat16 g_Wl[192 * C_];
// Projected Q, K bf16 hi/lo [B,T,64]; V transposed hi/lo [B,64,T].
__device__ __nv_bfloat16 g_Qh[B_ * T_ * H_];
__device__ __nv_bfloat16 g_Ql[B_ * T_ * H_];
__device__ __nv_bfloat16 g_Kh[B_ * T_ * H_];
__device__ __nv_bfloat16 g_Kl[B_ * T_ * H_];
__device__ __nv_bfloat16 g_Vth[B_ * H_ * T_];
__device__ __nv_bfloat16 g_Vtl[B_ * H_ * T_];
// Split-K attention partials.
__device__ float g_opart[SPLITS][B_ * T_ * H_];
__device__ float g_m[SPLITS][B_ * T_];
__device__ float g_l[SPLITS][B_ * T_];

// ---------------- bf16 hi/lo split + HMMA mma.sync helpers -----------------
__device__ __forceinline__ void cvt_pair(float a, float b,
                                         uint32_t& hi, uint32_t& lo) {
    __nv_bfloat16 ha = __float2bfloat16(a);
    __nv_bfloat16 hb = __float2bfloat16(b);
    __nv_bfloat16 la = __float2bfloat16(a - __bfloat162float(ha));
    __nv_bfloat16 lb = __float2bfloat16(b - __bfloat162float(hb));
    hi = (uint32_t)__bfloat16_as_ushort(ha) |
         ((uint32_t)__bfloat16_as_ushort(hb) << 16);
    lo = (uint32_t)__bfloat16_as_ushort(la) |
         ((uint32_t)__bfloat16_as_ushort(lb) << 16);
}
__device__ __forceinline__ void cvt_one(float a, uint16_t& hi, uint16_t& lo) {
    __nv_bfloat16 ha = __float2bfloat16(a);
    __nv_bfloat16 la = __float2bfloat16(a - __bfloat162float(ha));
    hi = __bfloat16_as_ushort(ha);
    lo = __bfloat16_as_ushort(la);
}
__device__ __forceinline__ void mma16816(float* d, const uint32_t* a,
                                         uint32_t b0, uint32_t b1) {
    asm volatile(
        "mma.sync.aligned.m16n8k16.row.col.f32.bf16.bf16.f32 "
        "{%0,%1,%2,%3}, {%4,%5,%6,%7}, {%8,%9}, {%0,%1,%2,%3};"
        : "+f"(d[0]), "+f"(d[1]), "+f"(d[2]), "+f"(d[3])
        : "r"(a[0]), "r"(a[1]), "r"(a[2]), "r"(a[3]), "r"(b0), "r"(b1));
}
__device__ __forceinline__ uint32_t cvta_s(const void* p) {
    return (uint32_t)__cvta_generic_to_shared(p);
}
#define LDMX4(R, addr)                                                        \
    asm volatile("ldmatrix.sync.aligned.m8n8.x4.shared.b16 {%0,%1,%2,%3}, [%4];" \
                 : "=r"((R)[0]), "=r"((R)[1]), "=r"((R)[2]), "=r"((R)[3])     \
                 : "r"(addr))
#define CPA16(dst, src)                                                       \
    asm volatile("cp.async.cg.shared.global [%0], [%1], 16;"                  \
                 :: "r"(dst), "l"(src))
#define CPA_COMMIT() asm volatile("cp.async.commit_group;" ::: "memory")
#define CPA_WAIT1()  asm volatile("cp.async.wait_group 1;" ::: "memory")
#define CPA_WAIT0()  asm volatile("cp.async.wait_group 0;" ::: "memory")

// ---------------------------------------------------------------------------
// Kernel 0: convert x and W to bf16 hi/lo once (bandwidth-bound).
// ---------------------------------------------------------------------------
__global__ __launch_bounds__(256)
void convert_kernel(const float* __restrict__ x,
                    const float* __restrict__ Wk,
                    const float* __restrict__ Wq,
                    const float* __restrict__ Wv) {
    const int t = threadIdx.x;
    const int bid = blockIdx.x;
    if (bid < 8192) {
        const size_t i0 = (size_t)bid * 2048 + (size_t)t * 8;
        const float4 v0 = *(const float4*)(x + i0);
        const float4 v1 = *(const float4*)(x + i0 + 4);
        uint32_t h0, l0, h1, l1, h2, l2, h3, l3;
        cvt_pair(v0.x, v0.y, h0, l0);
        cvt_pair(v0.z, v0.w, h1, l1);
        cvt_pair(v1.x, v1.y, h2, l2);
        cvt_pair(v1.z, v1.w, h3, l3);
        *(uint4*)(g_xh + i0) = make_uint4(h0, h1, h2, h3);
        *(uint4*)(g_xl + i0) = make_uint4(l0, l1, l2, l3);
    } else {
        const size_t off = (size_t)(bid - 8192) * 2048 + (size_t)t * 8;
        const int row = (int)(off >> 10);
        const int col = (int)(off & 1023);
        const float* src = (row < 64)  ? Wq + (size_t)row * C_ + col
                         : (row < 128) ? Wk + (size_t)(row - 64) * C_ + col
                                       : Wv + (size_t)(row - 128) * C_ + col;
        const float4 v0 = *(const float4*)(src);
        const float4 v1 = *(const float4*)(src + 4);
        uint32_t h0, l0, h1, l1, h2, l2, h3, l3;
        cvt_pair(v0.x, v0.y, h0, l0);
        cvt_pair(v0.z, v0.w, h1, l1);
        cvt_pair(v1.x, v1.y, h2, l2);
        cvt_pair(v1.z, v1.w, h3, l3);
        *(uint4*)(g_Wh + off) = make_uint4(h0, h1, h2, h3);
        *(uint4*)(g_Wl + off) = make_uint4(l0, l1, l2, l3);
    }
}

// ---------------------------------------------------------------------------
// Kernel 1: fused QKV projection — one CTA per 128-row M-tile computes ALL
// 192 output columns. Grid 128 (single wave). Block 256 = 8 warps (4x2),
// warp tile 32x96. cp.async double-buffered smem, ldmatrix fragments,
// bf16 hi/lo 3-pass HMMA.
// smem: A[2]{hi,lo}[128][72] + B[2]{hi,lo}[192][72] = 184320 B.
// ---------------------------------------------------------------------------
#define APAD 72
#define AS (128 * APAD)                 // A tile elems (one of hi/lo)
#define BS (192 * APAD)                 // B tile elems
#define PROJ_SMEM ((4 * AS + 4 * BS) * 2)

__global__ __launch_bounds__(256, 1)
void proj_mma_kernel() {
    extern __shared__ __nv_bfloat16 sb[];
    // layout: [Ahi0|Alo0|Ahi1|Alo1|Bhi0|Blo0|Bhi1|Blo1]
    const uint32_t smb = cvta_s(sb);

    const int t    = threadIdx.x;
    const int wid  = t >> 5;
    const int lane = t & 31;
    const int row0 = blockIdx.x * 128;
    const int wm = wid >> 1, wn = wid & 1;
    const int g = lane >> 2, c = lane & 3;

    // loader mappings
    const int arow = t >> 1, acol = (t & 1) * 32;   // A: 4 x 16B per buf-half

    // ldmatrix lane offsets (bytes within a tile)
    const uint32_t aoff =
        ((wm * 32 + (lane & 7) + ((lane >> 3) & 1) * 8) * APAD +
         (lane >> 4) * 8) * 2;
    const uint32_t boff =
        (((lane & 7) + (lane >> 4) * 8) * APAD + ((lane >> 3) & 1) * 8) * 2;

    // smem tile base offsets (bytes)
    const uint32_t oAhi[2] = { 0u, (uint32_t)(2 * AS * 2) };
    const uint32_t oBhi[2] = { (uint32_t)(4 * AS * 2),
                               (uint32_t)((4 * AS + 2 * BS) * 2) };

    auto issue_chunk = [&](int kc, int buf) {
        // A: hi + lo, 4 x 16B each (128 rows x 8 quads = 1024 = 256t x 4)
        {
            const uint32_t dh = smb + oAhi[buf] + (arow * APAD + acol) * 2;
            const uint32_t dl = dh + AS * 2;
            const __nv_bfloat16* sh =
                g_xh + (size_t)(row0 + arow) * C_ + kc * 64 + acol;
            const __nv_bfloat16* sl =
                g_xl + (size_t)(row0 + arow) * C_ + kc * 64 + acol;
            #pragma unroll
            for (int u = 0; u < 4; u++) {
                CPA16(dh + u * 16, sh + u * 8);
                CPA16(dl + u * 16, sl + u * 8);
            }
        }
        // B: hi + lo, 6 x 16B each (192 rows x 8 quads = 1536 = 256t x 6)
        #pragma unroll
        for (int u = 0; u < 6; u++) {
            const int idx = u * 256 + t;
            const int row = idx >> 3;
            const int c16 = (idx & 7) * 8;
            const uint32_t dh = smb + oBhi[buf] + (row * APAD + c16) * 2;
            CPA16(dh, g_Wh + (size_t)row * C_ + kc * 64 + c16);
            CPA16(dh + BS * 2, g_Wl + (size_t)row * C_ + kc * 64 + c16);
        }
        CPA_COMMIT();
    };

    float acc[2][12][4] = {};

    issue_chunk(0, 0);

    for (int kc = 0; kc < 16; kc++) {
        const int buf = kc & 1;
        if (kc < 15) issue_chunk(kc + 1, buf ^ 1);
        if (kc < 15) { CPA_WAIT1(); } else { CPA_WAIT0(); }
        __syncthreads();

        const uint32_t aHi = smb + oAhi[buf] + aoff;
        const uint32_t aLo = aHi + AS * 2;
        const uint32_t bHi = smb + oBhi[buf] + boff + (uint32_t)(wn * 96 * APAD * 2);
        const uint32_t bLo = bHi + BS * 2;

        #pragma unroll
        for (int pass = 0; pass < 3; pass++) {
            const uint32_t ab = (pass == 2) ? aLo : aHi;
            const uint32_t bb = (pass == 1) ? bLo : bHi;
            #pragma unroll
            for (int k16 = 0; k16 < 4; k16++) {
                uint32_t A0[4], A1[4];
                LDMX4(A0, ab + k16 * 32);
                LDMX4(A1, ab + 16 * APAD * 2 + k16 * 32);
                #pragma unroll
                for (int n16 = 0; n16 < 6; n16++) {
                    uint32_t Bf[4];
                    LDMX4(Bf, bb + n16 * 16 * APAD * 2 + k16 * 32);
                    mma16816(acc[0][n16 * 2 + 0], A0, Bf[0], Bf[1]);
                    mma16816(acc[0][n16 * 2 + 1], A0, Bf[2], Bf[3]);
                    mma16816(acc[1][n16 * 2 + 0], A1, Bf[0], Bf[1]);
                    mma16816(acc[1][n16 * 2 + 1], A1, Bf[2], Bf[3]);
                }
            }
        }
        __syncthreads();
    }

    // ---- epilogue: convert to bf16 hi/lo and store (Q | K | V^T) ----
    #pragma unroll
    for (int mi = 0; mi < 2; mi++) {
        const int r = row0 + wm * 32 + mi * 16 + g;
        #pragma unroll
        for (int nj = 0; nj < 12; nj++) {
            const int col = wn * 96 + nj * 8 + c * 2;
            if (col < 128) {
                __nv_bfloat16* dh = (col < 64) ? g_Qh : g_Kh;
                __nv_bfloat16* dl = (col < 64) ? g_Ql : g_Kl;
                const int cc = col & 63;
                uint32_t h01, l01, h23, l23;
                cvt_pair(acc[mi][nj][0], acc[mi][nj][1], h01, l01);
                cvt_pair(acc[mi][nj][2], acc[mi][nj][3], h23, l23);
                *(uint32_t*)(dh + (size_t)r * H_ + cc) = h01;
                *(uint32_t*)(dl + (size_t)r * H_ + cc) = l01;
                *(uint32_t*)(dh + (size_t)(r + 8) * H_ + cc) = h23;
                *(uint32_t*)(dl + (size_t)(r + 8) * H_ + cc) = l23;
            } else {
                // V transposed: g_Vt[b][c][t]
                const int bb = r >> 12;
                const int tt = r & (T_ - 1);
                #pragma unroll
                for (int u = 0; u < 4; u++) {
                    const int rr = (u >> 1) * 8;
                    const int cc = (col - 128) + (u & 1);
                    uint16_t h, l;
                    cvt_one(acc[mi][nj][u], h, l);
                    const size_t idx = ((size_t)bb * H_ + cc) * T_ + tt + rr;
                    *(uint16_t*)(g_Vth + idx) = h;
                    *(uint16_t*)(g_Vtl + idx) = l;
                }
            }
        }
    }
}

// ---------------------------------------------------------------------------
// Kernel 2: split-K flash attention on HMMA (unchanged).
// ---------------------------------------------------------------------------
#define TPAD 72
#define ATTN_SMEM (6 * 64 * TPAD * 2 + 2 * 128 * 4)

__global__ __launch_bounds__(256, 1)
void attn_mma_kernel() {
    extern __shared__ char smraw[];
    __nv_bfloat16* Khs = (__nv_bfloat16*)smraw;
    __nv_bfloat16* Kls = Khs + 64 * TPAD;
    __nv_bfloat16* Vhs = Kls + 64 * TPAD;
    __nv_bfloat16* Vls = Vhs + 64 * TPAD;
    __nv_bfloat16* Phs = Vls + 64 * TPAD;
    __nv_bfloat16* Pls = Phs + 64 * TPAD;
    float* redmax = (float*)(Pls + 64 * TPAD);
    float* redsum = redmax + 128;

    const int qb = blockIdx.x, sp = blockIdx.y, b = blockIdx.z;
    const int t = threadIdx.x, wid = t >> 5, lane = t & 31;
    const int wm = wid >> 1, wn = wid & 1;
    const int g = lane >> 2, c = lane & 3;
    const int lr = t >> 2, lc = (t & 3) * 16;

    const size_t base = (size_t)b * T_ * H_;
    const int row_a = wm * 16 + g;

    {
        const size_t off = base + (size_t)(qb * 64 + lr) * H_ + lc;
        *(uint4*)(Phs + lr * TPAD + lc)     = *(const uint4*)(g_Qh + off);
        *(uint4*)(Phs + lr * TPAD + lc + 8) = *(const uint4*)(g_Qh + off + 8);
        *(uint4*)(Pls + lr * TPAD + lc)     = *(const uint4*)(g_Ql + off);
        *(uint4*)(Pls + lr * TPAD + lc + 8) = *(const uint4*)(g_Ql + off + 8);
    }
    __syncthreads();
    uint32_t qh_f[4][4], ql_f[4][4];
    #pragma unroll
    for (int k = 0; k < 4; k++) {
        const __nv_bfloat16* ba = Phs + row_a * TPAD + k * 16 + c * 2;
        qh_f[k][0] = *(const uint32_t*)(ba);
        qh_f[k][1] = *(const uint32_t*)(ba + 8 * TPAD);
        qh_f[k][2] = *(const uint32_t*)(ba + 8);
        qh_f[k][3] = *(const uint32_t*)(ba + 8 * TPAD + 8);
        const __nv_bfloat16* bl = Pls + row_a * TPAD + k * 16 + c * 2;
        ql_f[k][0] = *(const uint32_t*)(bl);
        ql_f[k][1] = *(const uint32_t*)(bl + 8 * TPAD);
        ql_f[k][2] = *(const uint32_t*)(bl + 8);
        ql_f[k][3] = *(const uint32_t*)(bl + 8 * TPAD + 8);
    }
    __syncthreads();

    float o_acc[4][4] = {};
    float m0 = NEG_BIG, m1 = NEG_BIG, l0 = 0.0f, l1 = 0.0f;
    const float sc2 = 1.0f / 64.0f;
    const int kb_max = min(qb + 1, T_ / 64 - 1);

    for (int kb = sp; kb <= kb_max; kb += SPLITS) {
        {
            const size_t koff = base + (size_t)(kb * 64 + lr) * H_ + lc;
            *(uint4*)(Khs + lr * TPAD + lc)     = *(const uint4*)(g_Kh + koff);
            *(uint4*)(Khs + lr * TPAD + lc + 8) = *(const uint4*)(g_Kh + koff + 8);
            *(uint4*)(Kls + lr * TPAD + lc)     = *(const uint4*)(g_Kl + koff);
            *(uint4*)(Kls + lr * TPAD + lc + 8) = *(const uint4*)(g_Kl + koff + 8);
            const size_t voff = ((size_t)b * H_ + lr) * T_ + kb * 64 + lc;
            *(uint4*)(Vhs + lr * TPAD + lc)     = *(const uint4*)(g_Vth + voff);
            *(uint4*)(Vhs + lr * TPAD + lc + 8) = *(const uint4*)(g_Vth + voff + 8);
            *(uint4*)(Vls + lr * TPAD + lc)     = *(const uint4*)(g_Vtl + voff);
            *(uint4*)(Vls + lr * TPAD + lc + 8) = *(const uint4*)(g_Vtl + voff + 8);
        }
        __syncthreads();

        float s_acc[4][4] = {};
        #pragma unroll
        for (int k = 0; k < 4; k++) {
            #pragma unroll
            for (int ni = 0; ni < 4; ni++) {
                const int brow = (wn * 32 + ni * 8 + g) * TPAD + k * 16 + c * 2;
                const uint32_t bh0 = *(const uint32_t*)(Khs + brow);
                const uint32_t bh1 = *(const uint32_t*)(Khs + brow + 8);
                const uint32_t bl0 = *(const uint32_t*)(Kls + brow);
                const uint32_t bl1 = *(const uint32_t*)(Kls + brow + 8);
                mma16816(s_acc[ni], qh_f[k], bh0, bh1);
                mma16816(s_acc[ni], qh_f[k], bl0, bl1);
                mma16816(s_acc[ni], ql_f[k], bh0, bh1);
            }
        }

        const bool need_mask = (kb >= qb);
        const int i0 = qb * 64 + row_a;
        float sv[4][4];
        float rm0 = NEG_BIG, rm1 = NEG_BIG;
        #pragma unroll
        for (int ni = 0; ni < 4; ni++) {
            const int j0 = kb * 64 + wn * 32 + ni * 8 + c * 2;
            float v0 = s_acc[ni][0] * sc2;
            float v1 = s_acc[ni][1] * sc2;
            float v2 = s_acc[ni][2] * sc2;
            float v3 = s_acc[ni][3] * sc2;
            if (need_mask) {
                if (j0     > i0 + 1) v0 = NEG_BIG;
                if (j0 + 1 > i0 + 1) v1 = NEG_BIG;
                if (j0     > i0 + 9) v2 = NEG_BIG;
                if (j0 + 1 > i0 + 9) v3 = NEG_BIG;
            }
            sv[ni][0] = v0; sv[ni][1] = v1; sv[ni][2] = v2; sv[ni][3] = v3;
            rm0 = fmaxf(rm0, fmaxf(v0, v1));
            rm1 = fmaxf(rm1, fmaxf(v2, v3));
        }
        rm0 = fmaxf(rm0, __shfl_xor_sync(0xffffffffu, rm0, 1));
        rm0 = fmaxf(rm0, __shfl_xor_sync(0xffffffffu, rm0, 2));
        rm1 = fmaxf(rm1, __shfl_xor_sync(0xffffffffu, rm1, 1));
        rm1 = fmaxf(rm1, __shfl_xor_sync(0xffffffffu, rm1, 2));
        redmax[(row_a)     * 2 + wn] = rm0;
        redmax[(row_a + 8) * 2 + wn] = rm1;
        __syncthreads();
        rm0 = fmaxf(redmax[row_a * 2], redmax[row_a * 2 + 1]);
        rm1 = fmaxf(redmax[(row_a + 8) * 2], redmax[(row_a + 8) * 2 + 1]);
        const float mn0 = fmaxf(m0, rm0);
        const float mn1 = fmaxf(m1, rm1);
        const float f0 = __expf(m0 - mn0);
        const float f1 = __expf(m1 - mn1);
        m0 = mn0; m1 = mn1;

        float rs0 = 0.0f, rs1 = 0.0f;
        #pragma unroll
        for (int ni = 0; ni < 4; ni++) {
            const float e0 = (sv[ni][0] > -5e29f) ? __expf(sv[ni][0] - mn0) : 0.0f;
            const float e1 = (sv[ni][1] > -5e29f) ? __expf(sv[ni][1] - mn0) : 0.0f;
            const float e2 = (sv[ni][2] > -5e29f) ? __expf(sv[ni][2] - mn1) : 0.0f;
            const float e3 = (sv[ni][3] > -5e29f) ? __expf(sv[ni][3] - mn1) : 0.0f;
            rs0 += e0 + e1;
            rs1 += e2 + e3;
            uint32_t h01, l01, h23, l23;
            cvt_pair(e0, e1, h01, l01);
            cvt_pair(e2, e3, h23, l23);
            const int col = wn * 32 + ni * 8 + c * 2;
            *(uint32_t*)(Phs + (row_a)     * TPAD + col) = h01;
            *(uint32_t*)(Pls + (row_a)     * TPAD + col) = l01;
            *(uint32_t*)(Phs + (row_a + 8) * TPAD + col) = h23;
            *(uint32_t*)(Pls + (row_a + 8) * TPAD + col) = l23;
        }
        rs0 += __shfl_xor_sync(0xffffffffu, rs0, 1);
        rs0 += __shfl_xor_sync(0xffffffffu, rs0, 2);
        rs1 += __shfl_xor_sync(0xffffffffu, rs1, 1);
        rs1 += __shfl_xor_sync(0xffffffffu, rs1, 2);
        redsum[(row_a)     * 2 + wn] = rs0;
        redsum[(row_a + 8) * 2 + wn] = rs1;

        #pragma unroll
        for (int ni = 0; ni < 4; ni++) {
            o_acc[ni][0] *= f0; o_acc[ni][1] *= f0;
            o_acc[ni][2] *= f1; o_acc[ni][3] *= f1;
        }
        __syncthreads();
        l0 = l0 * f0 + redsum[row_a * 2] + redsum[row_a * 2 + 1];
        l1 = l1 * f1 + redsum[(row_a + 8) * 2] + redsum[(row_a + 8) * 2 + 1];

        #pragma unroll
        for (int k = 0; k < 4; k++) {
            uint32_t ph[4], pl[4];
            const __nv_bfloat16* pa = Phs + row_a * TPAD + k * 16 + c * 2;
            ph[0] = *(const uint32_t*)(pa);
            ph[1] = *(const uint32_t*)(pa + 8 * TPAD);
            ph[2] = *(const uint32_t*)(pa + 8);
            ph[3] = *(const uint32_t*)(pa + 8 * TPAD + 8);
            const __nv_bfloat16* pb = Pls + row_a * TPAD + k * 16 + c * 2;
            pl[0] = *(const uint32_t*)(pb);
            pl[1] = *(const uint32_t*)(pb + 8 * TPAD);
            pl[2] = *(const uint32_t*)(pb + 8);
            pl[3] = *(const uint32_t*)(pb + 8 * TPAD + 8);
            #pragma unroll
            for (int ni = 0; ni < 4; ni++) {
                const int brow = (wn * 32 + ni * 8 + g) * TPAD + k * 16 + c * 2;
                const uint32_t vh0 = *(const uint32_t*)(Vhs + brow);
                const uint32_t vh1 = *(const uint32_t*)(Vhs + brow + 8);
                const uint32_t vl0 = *(const uint32_t*)(Vls + brow);
                const uint32_t vl1 = *(const uint32_t*)(Vls + brow + 8);
                mma16816(o_acc[ni], ph, vh0, vh1);
                mma16816(o_acc[ni], ph, vl0, vl1);
                mma16816(o_acc[ni], pl, vh0, vh1);
            }
        }
        __syncthreads();
    }

    const size_t rb = (size_t)b * T_ + qb * 64;
    #pragma unroll
    for (int ni = 0; ni < 4; ni++) {
        const int col = wn * 32 + ni * 8 + c * 2;
        float2 v0; v0.x = o_acc[ni][0]; v0.y = o_acc[ni][1];
        float2 v1; v1.x = o_acc[ni][2]; v1.y = o_acc[ni][3];
        *(float2*)(g_opart[sp] + (rb + row_a) * 64 + col) = v0;
        *(float2*)(g_opart[sp] + (rb + row_a + 8) * 64 + col) = v1;
    }
    if (c == 0 && wn == 0) {
        g_m[sp][rb + row_a] = m0;
        g_l[sp][rb + row_a] = l0;
        g_m[sp][rb + row_a + 8] = m1;
        g_l[sp][rb + row_a + 8] = l1;
    }
}

// ---------------------------------------------------------------------------
// Kernel 3: combine split partials.
// ---------------------------------------------------------------------------
__global__ __launch_bounds__(256)
void combine_kernel(float* __restrict__ out) {
    const int t = threadIdx.x;
    const size_t r = (size_t)blockIdx.x * 16 + (t >> 4);
    const int c = (t & 15) * 4;

    float mv[SPLITS], lv[SPLITS];
    float M = NEG_BIG;
    #pragma unroll
    for (int s = 0; s < SPLITS; s++) {
        mv[s] = g_m[s][r];
        lv[s] = g_l[s][r];
        M = fmaxf(M, mv[s]);
    }
    float w[SPLITS], L = 0.0f;
    #pragma unroll
    for (int s = 0; s < SPLITS; s++) {
        w[s] = __expf(mv[s] - M);
        L += lv[s] * w[s];
    }
    float4 acc = make_float4(0.f, 0.f, 0.f, 0.f);
    #pragma unroll
    for (int s = 0; s < SPLITS; s++) {
        const float4 o = *(const float4*)(g_opart[s] + r * 64 + c);
        acc.x += w[s] * o.x; acc.y += w[s] * o.y;
        acc.z += w[s] * o.z; acc.w += w[s] * o.w;
    }
    const float inv = 1.0f / L;
    float4 ov;
    ov.x = acc.x * inv; ov.y = acc.y * inv;
    ov.z = acc.z * inv; ov.w = acc.w * inv;
    *(float4*)(out + r * 64 + c) = ov;
}

// ---------------------------------------------------------------------------
// Launch
// ---------------------------------------------------------------------------
extern "C" void kernel_launch(void* const* d_in, const int* in_sizes, int n_in,
                              void* d_out, int out_size) {
    const float* x  = (const float*)d_in[0];
    const float* Wk = (const float*)d_in[1];
    const float* Wq = (const float*)d_in[2];
    const float* Wv = (const float*)d_in[3];
    float* out = (float*)d_out;

    cudaFuncSetAttribute(proj_mma_kernel,
                         cudaFuncAttributeMaxDynamicSharedMemorySize, PROJ_SMEM);
    cudaFuncSetAttribute(attn_mma_kernel,
                         cudaFuncAttributeMaxDynamicSharedMemorySize, ATTN_SMEM);

    convert_kernel<<<8192 + 96, 256>>>(x, Wk, Wq, Wv);
    proj_mma_kernel<<<128, 256, PROJ_SMEM>>>();
    attn_mma_kernel<<<dim3(T_ / 64, SPLITS, B_), 256, ATTN_SMEM>>>();
    combine_kernel<<<(B_ * T_) / 16, 256>>>(out);
}

// round 13
// speedup vs baseline: 1.4166x; 1.1065x over previous
#include <cuda_runtime.h>
#include <cuda_bf16.h>
#include <cstdint>

#define B_ 4
#define T_ 4096
#define C_ 1024
#define H_ 64
#define SPLITS 4
#define NEG_BIG (-1e30f)

// Preconverted operands (bf16 hi/lo).
__device__ __nv_bfloat16 g_xh[B_ * T_ * C_];
__device__ __nv_bfloat16 g_xl[B_ * T_ * C_];
__device__ __nv_bfloat16 g_Wh[192 * C_];      // rows: [Wq(64); Wk(64); Wv(64)]
__device__ __nv_bfloat16 g_Wl[192 * C_];
// Projected Q hi/lo, K hi [B,T,64]; V transposed hi/lo [B,64,T].
__device__ __nv_bfloat16 g_Qh[B_ * T_ * H_];
__device__ __nv_bfloat16 g_Ql[B_ * T_ * H_];
__device__ __nv_bfloat16 g_Kh[B_ * T_ * H_];
__device__ __nv_bfloat16 g_Vth[B_ * H_ * T_];
__device__ __nv_bfloat16 g_Vtl[B_ * H_ * T_];
// Split-K attention partials.
__device__ float g_opart[SPLITS][B_ * T_ * H_];
__device__ float g_m[SPLITS][B_ * T_];
__device__ float g_l[SPLITS][B_ * T_];

// ---------------- bf16 hi/lo split + HMMA mma.sync helpers -----------------
__device__ __forceinline__ void cvt_pair(float a, float b,
                                         uint32_t& hi, uint32_t& lo) {
    __nv_bfloat16 ha = __float2bfloat16(a);
    __nv_bfloat16 hb = __float2bfloat16(b);
    __nv_bfloat16 la = __float2bfloat16(a - __bfloat162float(ha));
    __nv_bfloat16 lb = __float2bfloat16(b - __bfloat162float(hb));
    hi = (uint32_t)__bfloat16_as_ushort(ha) |
         ((uint32_t)__bfloat16_as_ushort(hb) << 16);
    lo = (uint32_t)__bfloat16_as_ushort(la) |
         ((uint32_t)__bfloat16_as_ushort(lb) << 16);
}
__device__ __forceinline__ void cvt_one(float a, uint16_t& hi, uint16_t& lo) {
    __nv_bfloat16 ha = __float2bfloat16(a);
    __nv_bfloat16 la = __float2bfloat16(a - __bfloat162float(ha));
    hi = __bfloat16_as_ushort(ha);
    lo = __bfloat16_as_ushort(la);
}
__device__ __forceinline__ void mma16816(float* d, const uint32_t* a,
                                         uint32_t b0, uint32_t b1) {
    asm volatile(
        "mma.sync.aligned.m16n8k16.row.col.f32.bf16.bf16.f32 "
        "{%0,%1,%2,%3}, {%4,%5,%6,%7}, {%8,%9}, {%0,%1,%2,%3};"
        : "+f"(d[0]), "+f"(d[1]), "+f"(d[2]), "+f"(d[3])
        : "r"(a[0]), "r"(a[1]), "r"(a[2]), "r"(a[3]), "r"(b0), "r"(b1));
}
__device__ __forceinline__ uint32_t cvta_s(const void* p) {
    return (uint32_t)__cvta_generic_to_shared(p);
}
#define LDMX4(R, addr)                                                        \
    asm volatile("ldmatrix.sync.aligned.m8n8.x4.shared.b16 {%0,%1,%2,%3}, [%4];" \
                 : "=r"((R)[0]), "=r"((R)[1]), "=r"((R)[2]), "=r"((R)[3])     \
                 : "r"(addr))
#define CPA16(dst, src)                                                       \
    asm volatile("cp.async.cg.shared.global [%0], [%1], 16;"                  \
                 :: "r"(dst), "l"(src))
#define CPA_COMMIT() asm volatile("cp.async.commit_group;" ::: "memory")
#define CPA_WAIT1()  asm volatile("cp.async.wait_group 1;" ::: "memory")
#define CPA_WAIT0()  asm volatile("cp.async.wait_group 0;" ::: "memory")

// ---------------------------------------------------------------------------
// Kernel 0: convert x and W to bf16 hi/lo once (bandwidth-bound).
// ---------------------------------------------------------------------------
__global__ __launch_bounds__(256)
void convert_kernel(const float* __restrict__ x,
                    const float* __restrict__ Wk,
                    const float* __restrict__ Wq,
                    const float* __restrict__ Wv) {
    const int t = threadIdx.x;
    const int bid = blockIdx.x;
    if (bid < 8192) {
        const size_t i0 = (size_t)bid * 2048 + (size_t)t * 8;
        const float4 v0 = *(const float4*)(x + i0);
        const float4 v1 = *(const float4*)(x + i0 + 4);
        uint32_t h0, l0, h1, l1, h2, l2, h3, l3;
        cvt_pair(v0.x, v0.y, h0, l0);
        cvt_pair(v0.z, v0.w, h1, l1);
        cvt_pair(v1.x, v1.y, h2, l2);
        cvt_pair(v1.z, v1.w, h3, l3);
        *(uint4*)(g_xh + i0) = make_uint4(h0, h1, h2, h3);
        *(uint4*)(g_xl + i0) = make_uint4(l0, l1, l2, l3);
    } else {
        const size_t off = (size_t)(bid - 8192) * 2048 + (size_t)t * 8;
        const int row = (int)(off >> 10);
        const int col = (int)(off & 1023);
        const float* src = (row < 64)  ? Wq + (size_t)row * C_ + col
                         : (row < 128) ? Wk + (size_t)(row - 64) * C_ + col
                                       : Wv + (size_t)(row - 128) * C_ + col;
        const float4 v0 = *(const float4*)(src);
        const float4 v1 = *(const float4*)(src + 4);
        uint32_t h0, l0, h1, l1, h2, l2, h3, l3;
        cvt_pair(v0.x, v0.y, h0, l0);
        cvt_pair(v0.z, v0.w, h1, l1);
        cvt_pair(v1.x, v1.y, h2, l2);
        cvt_pair(v1.z, v1.w, h3, l3);
        *(uint4*)(g_Wh + off) = make_uint4(h0, h1, h2, h3);
        *(uint4*)(g_Wl + off) = make_uint4(l0, l1, l2, l3);
    }
}

// ---------------------------------------------------------------------------
// Kernel 1: fused QKV projection — one CTA per 128-row M-tile, all 192 cols.
// Grid 128 (single wave). Block 256 = 8 warps (4x2), warp tile 32x96.
// cp.async double-buffered smem, ldmatrix fragments, 3-pass HMMA.
// V^T epilogue staged through smem for coalesced 16B stores.
// ---------------------------------------------------------------------------
#define APAD 72
#define AS (128 * APAD)                 // A tile elems (one of hi/lo)
#define BS (192 * APAD)                 // B tile elems
#define PROJ_SMEM ((4 * AS + 4 * BS) * 2)
#define VPAD 136                        // V^T staging row stride (elems)

__global__ __launch_bounds__(256, 1)
void proj_mma_kernel() {
    extern __shared__ __nv_bfloat16 sb[];
    // layout: [Ahi0|Alo0|Ahi1|Alo1|Bhi0|Blo0|Bhi1|Blo1]
    const uint32_t smb = cvta_s(sb);

    const int t    = threadIdx.x;
    const int wid  = t >> 5;
    const int lane = t & 31;
    const int row0 = blockIdx.x * 128;
    const int wm = wid >> 1, wn = wid & 1;
    const int g = lane >> 2, c = lane & 3;

    // loader mappings
    const int arow = t >> 1, acol = (t & 1) * 32;   // A: 4 x 16B per buf-half

    // ldmatrix lane offsets (bytes within a tile)
    const uint32_t aoff =
        ((wm * 32 + (lane & 7) + ((lane >> 3) & 1) * 8) * APAD +
         (lane >> 4) * 8) * 2;
    const uint32_t boff =
        (((lane & 7) + (lane >> 4) * 8) * APAD + ((lane >> 3) & 1) * 8) * 2;

    // smem tile base offsets (bytes)
    const uint32_t oAhi[2] = { 0u, (uint32_t)(2 * AS * 2) };
    const uint32_t oBhi[2] = { (uint32_t)(4 * AS * 2),
                               (uint32_t)((4 * AS + 2 * BS) * 2) };

    auto issue_chunk = [&](int kc, int buf) {
        // A: hi + lo, 4 x 16B each (128 rows x 8 quads = 1024 = 256t x 4)
        {
            const uint32_t dh = smb + oAhi[buf] + (arow * APAD + acol) * 2;
            const uint32_t dl = dh + AS * 2;
            const __nv_bfloat16* sh =
                g_xh + (size_t)(row0 + arow) * C_ + kc * 64 + acol;
            const __nv_bfloat16* sl =
                g_xl + (size_t)(row0 + arow) * C_ + kc * 64 + acol;
            #pragma unroll
            for (int u = 0; u < 4; u++) {
                CPA16(dh + u * 16, sh + u * 8);
                CPA16(dl + u * 16, sl + u * 8);
            }
        }
        // B: hi + lo, 6 x 16B each (192 rows x 8 quads = 1536 = 256t x 6)
        #pragma unroll
        for (int u = 0; u < 6; u++) {
            const int idx = u * 256 + t;
            const int row = idx >> 3;
            const int c16 = (idx & 7) * 8;
            const uint32_t dh = smb + oBhi[buf] + (row * APAD + c16) * 2;
            CPA16(dh, g_Wh + (size_t)row * C_ + kc * 64 + c16);
            CPA16(dh + BS * 2, g_Wl + (size_t)row * C_ + kc * 64 + c16);
        }
        CPA_COMMIT();
    };

    float acc[2][12][4] = {};

    issue_chunk(0, 0);

    for (int kc = 0; kc < 16; kc++) {
        const int buf = kc & 1;
        if (kc < 15) issue_chunk(kc + 1, buf ^ 1);
        if (kc < 15) { CPA_WAIT1(); } else { CPA_WAIT0(); }
        __syncthreads();

        const uint32_t aHi = smb + oAhi[buf] + aoff;
        const uint32_t aLo = aHi + AS * 2;
        const uint32_t bHi = smb + oBhi[buf] + boff + (uint32_t)(wn * 96 * APAD * 2);
        const uint32_t bLo = bHi + BS * 2;

        #pragma unroll
        for (int pass = 0; pass < 3; pass++) {
            const uint32_t ab = (pass == 2) ? aLo : aHi;
            const uint32_t bb = (pass == 1) ? bLo : bHi;
            #pragma unroll
            for (int k16 = 0; k16 < 4; k16++) {
                uint32_t A0[4], A1[4];
                LDMX4(A0, ab + k16 * 32);
                LDMX4(A1, ab + 16 * APAD * 2 + k16 * 32);
                #pragma unroll
                for (int n16 = 0; n16 < 6; n16++) {
                    uint32_t Bf[4];
                    LDMX4(Bf, bb + n16 * 16 * APAD * 2 + k16 * 32);
                    mma16816(acc[0][n16 * 2 + 0], A0, Bf[0], Bf[1]);
                    mma16816(acc[0][n16 * 2 + 1], A0, Bf[2], Bf[3]);
                    mma16816(acc[1][n16 * 2 + 0], A1, Bf[0], Bf[1]);
                    mma16816(acc[1][n16 * 2 + 1], A1, Bf[2], Bf[3]);
                }
            }
        }
        __syncthreads();
    }

    // ---- epilogue part 1: Q (hi+lo), K (hi only) direct stores;
    //      V staged into smem transpose buffers ----
    __nv_bfloat16* Vts_h = sb;                 // [64][VPAD]
    __nv_bfloat16* Vts_l = sb + 64 * VPAD;

    #pragma unroll
    for (int mi = 0; mi < 2; mi++) {
        const int r = row0 + wm * 32 + mi * 16 + g;
        #pragma unroll
        for (int nj = 0; nj < 12; nj++) {
            const int col = wn * 96 + nj * 8 + c * 2;
            if (col < 64) {
                uint32_t h01, l01, h23, l23;
                cvt_pair(acc[mi][nj][0], acc[mi][nj][1], h01, l01);
                cvt_pair(acc[mi][nj][2], acc[mi][nj][3], h23, l23);
                *(uint32_t*)(g_Qh + (size_t)r * H_ + col) = h01;
                *(uint32_t*)(g_Ql + (size_t)r * H_ + col) = l01;
                *(uint32_t*)(g_Qh + (size_t)(r + 8) * H_ + col) = h23;
                *(uint32_t*)(g_Ql + (size_t)(r + 8) * H_ + col) = l23;
            } else if (col < 128) {
                const int cc = col - 64;
                uint32_t h01, l01, h23, l23;
                cvt_pair(acc[mi][nj][0], acc[mi][nj][1], h01, l01);
                cvt_pair(acc[mi][nj][2], acc[mi][nj][3], h23, l23);
                *(uint32_t*)(g_Kh + (size_t)r * H_ + cc) = h01;
                *(uint32_t*)(g_Kh + (size_t)(r + 8) * H_ + cc) = h23;
            } else {
                const int cc = col - 128;
                const int rl = wm * 32 + mi * 16 + g;
                #pragma unroll
                for (int u = 0; u < 4; u++) {
                    uint16_t h, l;
                    cvt_one(acc[mi][nj][u], h, l);
                    const int ci = cc + (u & 1);
                    const int ri = rl + (u >> 1) * 8;
                    *(uint16_t*)(Vts_h + ci * VPAD + ri) = h;
                    *(uint16_t*)(Vts_l + ci * VPAD + ri) = l;
                }
            }
        }
    }
    __syncthreads();

    // ---- epilogue part 2: coalesced V^T stores (16B each) ----
    {
        const int cc = t >> 2;             // 0..63
        const int q4 = (t & 3) * 32;       // 32 elems per thread
        const int bb = row0 >> 12;
        const int tt0 = row0 & (T_ - 1);
        const size_t gidx = ((size_t)bb * H_ + cc) * T_ + tt0 + q4;
        #pragma unroll
        for (int u = 0; u < 4; u++) {
            *(uint4*)(g_Vth + gidx + u * 8) =
                *(const uint4*)(Vts_h + cc * VPAD + q4 + u * 8);
            *(uint4*)(g_Vtl + gidx + u * 8) =
                *(const uint4*)(Vts_l + cc * VPAD + q4 + u * 8);
        }
    }
}

// ---------------------------------------------------------------------------
// Kernel 2: split-K flash attention on HMMA.
// S-pass: 2 terms (Qh+Ql)·Kh — K low half dropped (exponent err ~2.5e-4).
// PV: 3 terms (PhVh + PhVl + PlVh).
// smem: Kh,Vh,Vl,Ph,Pl tiles 64x72 bf16 + reductions = 47104 B.
// ---------------------------------------------------------------------------
#define TPAD 72
#define ATTN_SMEM (5 * 64 * TPAD * 2 + 2 * 128 * 4)

__global__ __launch_bounds__(256, 1)
void attn_mma_kernel() {
    extern __shared__ char smraw[];
    __nv_bfloat16* Khs = (__nv_bfloat16*)smraw;
    __nv_bfloat16* Vhs = Khs + 64 * TPAD;
    __nv_bfloat16* Vls = Vhs + 64 * TPAD;
    __nv_bfloat16* Phs = Vls + 64 * TPAD;
    __nv_bfloat16* Pls = Phs + 64 * TPAD;
    float* redmax = (float*)(Pls + 64 * TPAD);
    float* redsum = redmax + 128;

    const int qb = blockIdx.x, sp = blockIdx.y, b = blockIdx.z;
    const int t = threadIdx.x, wid = t >> 5, lane = t & 31;
    const int wm = wid >> 1, wn = wid & 1;
    const int g = lane >> 2, c = lane & 3;
    const int lr = t >> 2, lc = (t & 3) * 16;

    const size_t base = (size_t)b * T_ * H_;
    const int row_a = wm * 16 + g;

    {
        const size_t off = base + (size_t)(qb * 64 + lr) * H_ + lc;
        *(uint4*)(Phs + lr * TPAD + lc)     = *(const uint4*)(g_Qh + off);
        *(uint4*)(Phs + lr * TPAD + lc + 8) = *(const uint4*)(g_Qh + off + 8);
        *(uint4*)(Pls + lr * TPAD + lc)     = *(const uint4*)(g_Ql + off);
        *(uint4*)(Pls + lr * TPAD + lc + 8) = *(const uint4*)(g_Ql + off + 8);
    }
    __syncthreads();
    uint32_t qh_f[4][4], ql_f[4][4];
    #pragma unroll
    for (int k = 0; k < 4; k++) {
        const __nv_bfloat16* ba = Phs + row_a * TPAD + k * 16 + c * 2;
        qh_f[k][0] = *(const uint32_t*)(ba);
        qh_f[k][1] = *(const uint32_t*)(ba + 8 * TPAD);
        qh_f[k][2] = *(const uint32_t*)(ba + 8);
        qh_f[k][3] = *(const uint32_t*)(ba + 8 * TPAD + 8);
        const __nv_bfloat16* bl = Pls + row_a * TPAD + k * 16 + c * 2;
        ql_f[k][0] = *(const uint32_t*)(bl);
        ql_f[k][1] = *(const uint32_t*)(bl + 8 * TPAD);
        ql_f[k][2] = *(const uint32_t*)(bl + 8);
        ql_f[k][3] = *(const uint32_t*)(bl + 8 * TPAD + 8);
    }
    __syncthreads();

    float o_acc[4][4] = {};
    float m0 = NEG_BIG, m1 = NEG_BIG, l0 = 0.0f, l1 = 0.0f;
    const float sc2 = 1.0f / 64.0f;
    const int kb_max = min(qb + 1, T_ / 64 - 1);

    for (int kb = sp; kb <= kb_max; kb += SPLITS) {
        {
            const size_t koff = base + (size_t)(kb * 64 + lr) * H_ + lc;
            *(uint4*)(Khs + lr * TPAD + lc)     = *(const uint4*)(g_Kh + koff);
            *(uint4*)(Khs + lr * TPAD + lc + 8) = *(const uint4*)(g_Kh + koff + 8);
            const size_t voff = ((size_t)b * H_ + lr) * T_ + kb * 64 + lc;
            *(uint4*)(Vhs + lr * TPAD + lc)     = *(const uint4*)(g_Vth + voff);
            *(uint4*)(Vhs + lr * TPAD + lc + 8) = *(const uint4*)(g_Vth + voff + 8);
            *(uint4*)(Vls + lr * TPAD + lc)     = *(const uint4*)(g_Vtl + voff);
            *(uint4*)(Vls + lr * TPAD + lc + 8) = *(const uint4*)(g_Vtl + voff + 8);
        }
        __syncthreads();

        float s_acc[4][4] = {};
        #pragma unroll
        for (int k = 0; k < 4; k++) {
            #pragma unroll
            for (int ni = 0; ni < 4; ni++) {
                const int brow = (wn * 32 + ni * 8 + g) * TPAD + k * 16 + c * 2;
                const uint32_t bh0 = *(const uint32_t*)(Khs + brow);
                const uint32_t bh1 = *(const uint32_t*)(Khs + brow + 8);
                mma16816(s_acc[ni], qh_f[k], bh0, bh1);
                mma16816(s_acc[ni], ql_f[k], bh0, bh1);
            }
        }

        const bool need_mask = (kb >= qb);
        const int i0 = qb * 64 + row_a;
        float sv[4][4];
        float rm0 = NEG_BIG, rm1 = NEG_BIG;
        #pragma unroll
        for (int ni = 0; ni < 4; ni++) {
            const int j0 = kb * 64 + wn * 32 + ni * 8 + c * 2;
            float v0 = s_acc[ni][0] * sc2;
            float v1 = s_acc[ni][1] * sc2;
            float v2 = s_acc[ni][2] * sc2;
            float v3 = s_acc[ni][3] * sc2;
            if (need_mask) {
                if (j0     > i0 + 1) v0 = NEG_BIG;
                if (j0 + 1 > i0 + 1) v1 = NEG_BIG;
                if (j0     > i0 + 9) v2 = NEG_BIG;
                if (j0 + 1 > i0 + 9) v3 = NEG_BIG;
            }
            sv[ni][0] = v0; sv[ni][1] = v1; sv[ni][2] = v2; sv[ni][3] = v3;
            rm0 = fmaxf(rm0, fmaxf(v0, v1));
            rm1 = fmaxf(rm1, fmaxf(v2, v3));
        }
        rm0 = fmaxf(rm0, __shfl_xor_sync(0xffffffffu, rm0, 1));
        rm0 = fmaxf(rm0, __shfl_xor_sync(0xffffffffu, rm0, 2));
        rm1 = fmaxf(rm1, __shfl_xor_sync(0xffffffffu, rm1, 1));
        rm1 = fmaxf(rm1, __shfl_xor_sync(0xffffffffu, rm1, 2));
        redmax[(row_a)     * 2 + wn] = rm0;
        redmax[(row_a + 8) * 2 + wn] = rm1;
        __syncthreads();
        rm0 = fmaxf(redmax[row_a * 2], redmax[row_a * 2 + 1]);
        rm1 = fmaxf(redmax[(row_a + 8) * 2], redmax[(row_a + 8) * 2 + 1]);
        const float mn0 = fmaxf(m0, rm0);
        const float mn1 = fmaxf(m1, rm1);
        const float f0 = __expf(m0 - mn0);
        const float f1 = __expf(m1 - mn1);
        m0 = mn0; m1 = mn1;

        float rs0 = 0.0f, rs1 = 0.0f;
        #pragma unroll
        for (int ni = 0; ni < 4; ni++) {
            const float e0 = (sv[ni][0] > -5e29f) ? __expf(sv[ni][0] - mn0) : 0.0f;
            const float e1 = (sv[ni][1] > -5e29f) ? __expf(sv[ni][1] - mn0) : 0.0f;
            const float e2 = (sv[ni][2] > -5e29f) ? __expf(sv[ni][2] - mn1) : 0.0f;
            const float e3 = (sv[ni][3] > -5e29f) ? __expf(sv[ni][3] - mn1) : 0.0f;
            rs0 += e0 + e1;
            rs1 += e2 + e3;
            uint32_t h01, l01, h23, l23;
            cvt_pair(e0, e1, h01, l01);
            cvt_pair(e2, e3, h23, l23);
            const int col = wn * 32 + ni * 8 + c * 2;
            *(uint32_t*)(Phs + (row_a)     * TPAD + col) = h01;
            *(uint32_t*)(Pls + (row_a)     * TPAD + col) = l01;
            *(uint32_t*)(Phs + (row_a + 8) * TPAD + col) = h23;
            *(uint32_t*)(Pls + (row_a + 8) * TPAD + col) = l23;
        }
        rs0 += __shfl_xor_sync(0xffffffffu, rs0, 1);
        rs0 += __shfl_xor_sync(0xffffffffu, rs0, 2);
        rs1 += __shfl_xor_sync(0xffffffffu, rs1, 1);
        rs1 += __shfl_xor_sync(0xffffffffu, rs1, 2);
        redsum[(row_a)     * 2 + wn] = rs0;
        redsum[(row_a + 8) * 2 + wn] = rs1;

        #pragma unroll
        for (int ni = 0; ni < 4; ni++) {
            o_acc[ni][0] *= f0; o_acc[ni][1] *= f0;
            o_acc[ni][2] *= f1; o_acc[ni][3] *= f1;
        }
        __syncthreads();
        l0 = l0 * f0 + redsum[row_a * 2] + redsum[row_a * 2 + 1];
        l1 = l1 * f1 + redsum[(row_a + 8) * 2] + redsum[(row_a + 8) * 2 + 1];

        #pragma unroll
        for (int k = 0; k < 4; k++) {
            uint32_t ph[4], pl[4];
            const __nv_bfloat16* pa = Phs + row_a * TPAD + k * 16 + c * 2;
            ph[0] = *(const uint32_t*)(pa);
            ph[1] = *(const uint32_t*)(pa + 8 * TPAD);
            ph[2] = *(const uint32_t*)(pa + 8);
            ph[3] = *(const uint32_t*)(pa + 8 * TPAD + 8);
            const __nv_bfloat16* pb = Pls + row_a * TPAD + k * 16 + c * 2;
            pl[0] = *(const uint32_t*)(pb);
            pl[1] = *(const uint32_t*)(pb + 8 * TPAD);
            pl[2] = *(const uint32_t*)(pb + 8);
            pl[3] = *(const uint32_t*)(pb + 8 * TPAD + 8);
            #pragma unroll
            for (int ni = 0; ni < 4; ni++) {
                const int brow = (wn * 32 + ni * 8 + g) * TPAD + k * 16 + c * 2;
                const uint32_t vh0 = *(const uint32_t*)(Vhs + brow);
                const uint32_t vh1 = *(const uint32_t*)(Vhs + brow + 8);
                const uint32_t vl0 = *(const uint32_t*)(Vls + brow);
                const uint32_t vl1 = *(const uint32_t*)(Vls + brow + 8);
                mma16816(o_acc[ni], ph, vh0, vh1);
                mma16816(o_acc[ni], ph, vl0, vl1);
                mma16816(o_acc[ni], pl, vh0, vh1);
            }
        }
        __syncthreads();
    }

    const size_t rb = (size_t)b * T_ + qb * 64;
    #pragma unroll
    for (int ni = 0; ni < 4; ni++) {
        const int col = wn * 32 + ni * 8 + c * 2;
        float2 v0; v0.x = o_acc[ni][0]; v0.y = o_acc[ni][1];
        float2 v1; v1.x = o_acc[ni][2]; v1.y = o_acc[ni][3];
        *(float2*)(g_opart[sp] + (rb + row_a) * 64 + col) = v0;
        *(float2*)(g_opart[sp] + (rb + row_a + 8) * 64 + col) = v1;
    }
    if (c == 0 && wn == 0) {
        g_m[sp][rb + row_a] = m0;
        g_l[sp][rb + row_a] = l0;
        g_m[sp][rb + row_a + 8] = m1;
        g_l[sp][rb + row_a + 8] = l1;
    }
}

// ---------------------------------------------------------------------------
// Kernel 3: combine split partials.
// ---------------------------------------------------------------------------
__global__ __launch_bounds__(256)
void combine_kernel(float* __restrict__ out) {
    const int t = threadIdx.x;
    const size_t r = (size_t)blockIdx.x * 16 + (t >> 4);
    const int c = (t & 15) * 4;

    float mv[SPLITS], lv[SPLITS];
    float M = NEG_BIG;
    #pragma unroll
    for (int s = 0; s < SPLITS; s++) {
        mv[s] = g_m[s][r];
        lv[s] = g_l[s][r];
        M = fmaxf(M, mv[s]);
    }
    float w[SPLITS], L = 0.0f;
    #pragma unroll
    for (int s = 0; s < SPLITS; s++) {
        w[s] = __expf(mv[s] - M);
        L += lv[s] * w[s];
    }
    float4 acc = make_float4(0.f, 0.f, 0.f, 0.f);
    #pragma unroll
    for (int s = 0; s < SPLITS; s++) {
        const float4 o = *(const float4*)(g_opart[s] + r * 64 + c);
        acc.x += w[s] * o.x; acc.y += w[s] * o.y;
        acc.z += w[s] * o.z; acc.w += w[s] * o.w;
    }
    const float inv = 1.0f / L;
    float4 ov;
    ov.x = acc.x * inv; ov.y = acc.y * inv;
    ov.z = acc.z * inv; ov.w = acc.w * inv;
    *(float4*)(out + r * 64 + c) = ov;
}

// ---------------------------------------------------------------------------
// Launch
// ---------------------------------------------------------------------------
extern "C" void kernel_launch(void* const* d_in, const int* in_sizes, int n_in,
                              void* d_out, int out_size) {
    const float* x  = (const float*)d_in[0];
    const float* Wk = (const float*)d_in[1];
    const float* Wq = (const float*)d_in[2];
    const float* Wv = (const float*)d_in[3];
    float* out = (float*)d_out;

    cudaFuncSetAttribute(proj_mma_kernel,
                         cudaFuncAttributeMaxDynamicSharedMemorySize, PROJ_SMEM);
    cudaFuncSetAttribute(attn_mma_kernel,
                         cudaFuncAttributeMaxDynamicSharedMemorySize, ATTN_SMEM);

    convert_kernel<<<8192 + 96, 256>>>(x, Wk, Wq, Wv);
    proj_mma_kernel<<<128, 256, PROJ_SMEM>>>();
    attn_mma_kernel<<<dim3(T_ / 64, SPLITS, B_), 256, ATTN_SMEM>>>();
    combine_kernel<<<(B_ * T_) / 16, 256>>>(out);
}